// round 11
// baseline (speedup 1.0000x reference)
#include <cuda_runtime.h>

#define FULL_MASK 0xFFFFFFFFu
#define S 128  // samples per ray

__global__ __launch_bounds__(64)
void nerf_render_kernel(const float* __restrict__ t,
                        const float* __restrict__ sigma,
                        const float* __restrict__ color,
                        float* __restrict__ out,
                        int N)
{
    const int warp_id = (blockIdx.x * blockDim.x + threadIdx.x) >> 5;  // ray index
    if (warp_id >= N) return;
    const int lane = threadIdx.x & 31;

    const float4* __restrict__ t4p = (const float4*)(t     + (size_t)warp_id * S);
    const float4* __restrict__ s4p = (const float4*)(sigma + (size_t)warp_id * S);
    const float4* __restrict__ c4p = (const float4*)(color + (size_t)warp_id * S * 3);

    // ---- Best measured policy: reads evict-first via L1, stores default ----
    const float4 tv = __ldcs(&t4p[lane]);
    const float4 sv = __ldcs(&s4p[lane]);
    const float4 ca = __ldcs(&c4p[3 * lane + 0]);  // s0.r s0.g s0.b s1.r
    const float4 cb = __ldcs(&c4p[3 * lane + 1]);  // s1.g s1.b s2.r s2.g
    const float4 cc = __ldcs(&c4p[3 * lane + 2]);  // s2.b s3.r s3.g s3.b

    // dt: forward differences; last sample of ray gets dt = 0 (infinite=False)
    const float t_next = __shfl_down_sync(FULL_MASK, tv.x, 1);  // sample 4l+4
    const float NL2E = -1.4426950408889634f;  // -log2(e)
    const float s0 = sv.x * (tv.y - tv.x) * NL2E;
    const float s1 = sv.y * (tv.z - tv.y) * NL2E;
    const float s2 = sv.z * (tv.w - tv.z) * NL2E;
    const float s3 = (lane == 31) ? 0.0f : sv.w * (t_next - tv.w) * NL2E;

    const float c0 = s0;
    const float c1 = c0 + s1;
    const float c2 = c1 + s2;
    const float c3 = c2 + s3;

    // Warp-inclusive scan of per-lane totals -> exclusive prefix for this lane
    float v = c3;
    #pragma unroll
    for (int off = 1; off < 32; off <<= 1) {
        float n = __shfl_up_sync(FULL_MASK, v, off);
        if (lane >= off) v += n;
    }
    const float excl = v - c3;

    // wi[j] = exp2(L[j-1]) - exp2(L[j])  (L = -log2e * cumsum(sdt))
    const float e0 = exp2f(excl + c0);
    const float e1 = exp2f(excl + c1);
    const float e2 = exp2f(excl + c2);
    const float e3 = exp2f(excl + c3);
    float e_prev = __shfl_up_sync(FULL_MASK, e3, 1);
    if (lane == 0) e_prev = 1.0f;  // T[0] = 1

    const float w0 = e_prev - e0;
    const float w1 = e0 - e1;
    const float w2 = e1 - e2;
    const float w3 = e2 - e3;

    // ---- Bulk stores early (default policy): drain during the reduction ----
    const size_t Nsz = (size_t)N;
    float4* __restrict__ wi_out = (float4*)(out + 4 * Nsz) + (size_t)warp_id * (S / 4);
    wi_out[lane] = make_float4(w0, w1, w2, w3);
    float4* __restrict__ t_out  = (float4*)(out + 4 * Nsz + Nsz * S) + (size_t)warp_id * (S / 4);
    t_out[lane] = tv;

    float r = w0 * ca.x + w1 * ca.w + w2 * cb.z + w3 * cc.y;
    float g = w0 * ca.y + w1 * cb.x + w2 * cb.w + w3 * cc.z;
    float b = w0 * ca.z + w1 * cb.y + w2 * cc.x + w3 * cc.w;
    float d = w0 * tv.x + w1 * tv.y + w2 * tv.z + w3 * tv.w;

    // ---- Transposed 4-value warp reduction: 14 shuffles instead of 20 ----
    #pragma unroll
    for (int off = 16; off >= 4; off >>= 1) {
        r += __shfl_xor_sync(FULL_MASK, r, off);
        g += __shfl_xor_sync(FULL_MASK, g, off);
        b += __shfl_xor_sync(FULL_MASK, b, off);
        d += __shfl_xor_sync(FULL_MASK, d, off);
    }
    // lanes 0-3 carry r-partials, 4-7 g, 8-11 b, 12-15 d (lane&3 = group id)
    float x = (lane < 8) ? ((lane < 4) ? r : g)
                         : ((lane < 12) ? b : d);
    x += __shfl_xor_sync(FULL_MASK, x, 2);
    x += __shfl_xor_sync(FULL_MASK, x, 1);
    // Totals: lane 0 -> r, lane 4 -> g, lane 8 -> b, lane 12 -> d
    if (lane == 0)       out[(size_t)warp_id * 3 + 0] = x;
    else if (lane == 4)  out[(size_t)warp_id * 3 + 1] = x;
    else if (lane == 8)  out[(size_t)warp_id * 3 + 2] = x;
    else if (lane == 12) out[3 * Nsz + warp_id]       = x;
}

extern "C" void kernel_launch(void* const* d_in, const int* in_sizes, int n_in,
                              void* d_out, int out_size) {
    const float* t     = (const float*)d_in[0];
    const float* sigma = (const float*)d_in[1];
    const float* color = (const float*)d_in[2];
    float* out = (float*)d_out;

    const int N = in_sizes[0] / S;   // rays
    const int threads = 64;          // 2 warps/block: fine-grained CTA backfill
    const int warps_per_block = threads / 32;
    const int blocks = (N + warps_per_block - 1) / warps_per_block;
    nerf_render_kernel<<<blocks, threads>>>(t, sigma, color, out, N);
}

// round 12
// speedup vs baseline: 1.0113x; 1.0113x over previous
#include <cuda_runtime.h>

#define FULL_MASK 0xFFFFFFFFu
#define S 128  // samples per ray

__global__ __launch_bounds__(64)
void nerf_render_kernel(const float* __restrict__ t,
                        const float* __restrict__ sigma,
                        const float* __restrict__ color,
                        float* __restrict__ out,
                        int N)
{
    const int warp_id = (blockIdx.x * blockDim.x + threadIdx.x) >> 5;  // ray index
    if (warp_id >= N) return;
    const int lane = threadIdx.x & 31;

    const float4* __restrict__ t4p = (const float4*)(t     + (size_t)warp_id * S);
    const float4* __restrict__ s4p = (const float4*)(sigma + (size_t)warp_id * S);
    const float4* __restrict__ c4p = (const float4*)(color + (size_t)warp_id * S * 3);

    // ---- Best measured policy: reads evict-first via L1, stores default ----
    const float4 tv = __ldcs(&t4p[lane]);
    const float4 sv = __ldcs(&s4p[lane]);
    const float4 ca = __ldcs(&c4p[3 * lane + 0]);  // s0.r s0.g s0.b s1.r
    const float4 cb = __ldcs(&c4p[3 * lane + 1]);  // s1.g s1.b s2.r s2.g
    const float4 cc = __ldcs(&c4p[3 * lane + 2]);  // s2.b s3.r s3.g s3.b

    // dt: forward differences; last sample of ray gets dt = 0 (infinite=False)
    const float t_next = __shfl_down_sync(FULL_MASK, tv.x, 1);  // sample 4l+4
    const float NL2E = -1.4426950408889634f;  // -log2(e)
    const float s0 = sv.x * (tv.y - tv.x) * NL2E;
    const float s1 = sv.y * (tv.z - tv.y) * NL2E;
    const float s2 = sv.z * (tv.w - tv.z) * NL2E;
    const float s3 = (lane == 31) ? 0.0f : sv.w * (t_next - tv.w) * NL2E;

    const float c0 = s0;
    const float c1 = c0 + s1;
    const float c2 = c1 + s2;
    const float c3 = c2 + s3;

    // Warp-inclusive scan of per-lane totals -> exclusive prefix for this lane
    float v = c3;
    #pragma unroll
    for (int off = 1; off < 32; off <<= 1) {
        float n = __shfl_up_sync(FULL_MASK, v, off);
        if (lane >= off) v += n;
    }
    const float excl = v - c3;

    // wi[j] = exp2(L[j-1]) - exp2(L[j])  (L = -log2e * cumsum(sdt))
    const float e0 = exp2f(excl + c0);
    const float e1 = exp2f(excl + c1);
    const float e2 = exp2f(excl + c2);
    const float e3 = exp2f(excl + c3);
    float e_prev = __shfl_up_sync(FULL_MASK, e3, 1);
    if (lane == 0) e_prev = 1.0f;  // T[0] = 1

    const float w0 = e_prev - e0;
    const float w1 = e0 - e1;
    const float w2 = e1 - e2;
    const float w3 = e2 - e3;

    // ---- Bulk stores early (default policy): drain during the reduction ----
    const size_t Nsz = (size_t)N;
    float4* __restrict__ wi_out = (float4*)(out + 4 * Nsz) + (size_t)warp_id * (S / 4);
    wi_out[lane] = make_float4(w0, w1, w2, w3);
    float4* __restrict__ t_out  = (float4*)(out + 4 * Nsz + Nsz * S) + (size_t)warp_id * (S / 4);
    t_out[lane] = tv;

    float r = w0 * ca.x + w1 * ca.w + w2 * cb.z + w3 * cc.y;
    float g = w0 * ca.y + w1 * cb.x + w2 * cb.w + w3 * cc.z;
    float b = w0 * ca.z + w1 * cb.y + w2 * cc.x + w3 * cc.w;
    float d = w0 * tv.x + w1 * tv.y + w2 * tv.z + w3 * tv.w;

    // Warp reduction
    #pragma unroll
    for (int off = 16; off > 0; off >>= 1) {
        r += __shfl_down_sync(FULL_MASK, r, off);
        g += __shfl_down_sync(FULL_MASK, g, off);
        b += __shfl_down_sync(FULL_MASK, b, off);
        d += __shfl_down_sync(FULL_MASK, d, off);
    }

    if (lane == 0) {
        out[(size_t)warp_id * 3 + 0] = r;
        out[(size_t)warp_id * 3 + 1] = g;
        out[(size_t)warp_id * 3 + 2] = b;
        out[3 * Nsz + warp_id]       = d;
    }
}

extern "C" void kernel_launch(void* const* d_in, const int* in_sizes, int n_in,
                              void* d_out, int out_size) {
    const float* t     = (const float*)d_in[0];
    const float* sigma = (const float*)d_in[1];
    const float* color = (const float*)d_in[2];
    float* out = (float*)d_out;

    const int N = in_sizes[0] / S;   // rays
    const int threads = 64;          // 2 warps/block: fine-grained CTA backfill
    const int warps_per_block = threads / 32;
    const int blocks = (N + warps_per_block - 1) / warps_per_block;
    nerf_render_kernel<<<blocks, threads>>>(t, sigma, color, out, N);
}